// round 14
// baseline (speedup 1.0000x reference)
#include <cuda_runtime.h>
#include <cuda_bf16.h>
#include <cuda_fp16.h>
#include <math.h>
#include <stdint.h>

#define SEQ   4096
#define HID   2048
#define NHQ   32
#define NHKV  4
#define DH    128
#define DQTOT (NHQ*DH)
#define DKVTOT (NHKV*DH)

// int8 cross-term scales
#define SXH_INV (127.0f / 8.0f)
#define SXL_INV (4064.0f)           // 127*256/8
#define SWH_INV (1016.0f)           // 127/0.125
#define SWL_INV (260096.0f)         // 1016*256
#define CSCALE  (1.0f / (127.0f * 127.0f * 256.0f))

// ---------------- scratch ----------------
__device__ uint4 g_XhiQ[(HID/16) * (SEQ/16) * 32];
__device__ uint4 g_XloQ[(HID/16) * (SEQ/16) * 32];
__device__ uint4 g_XhQ [(HID/16) * (SEQ/16) * 32];
__device__ uint4 g_X8h [(HID/32) * (SEQ/16) * 32];
__device__ uint4 g_X8l [(HID/32) * (SEQ/16) * 32];
__device__ uint2 g_WqHiP[(HID/16) * DQTOT * 4];
__device__ uint4 g_Wq8[(HID/32) * DQTOT * 4];
__device__ uint4 g_WkT[(HID/16) * DKVTOT * 4];
__device__ uint2 g_WvT[(HID/16) * DKVTOT * 4];
__device__ uint2 g_WoT[(DQTOT/16) * HID * 4];
__device__ __nv_bfloat16 g_Qhi[SEQ * DQTOT];
__device__ __nv_bfloat16 g_Qlo[SEQ * DQTOT];
__device__ uint4 g_KP[NHKV * 8 * SEQ * 4];
__device__ uint2 g_VP[NHKV * DH * (SEQ/16) * 4];
__device__ uint4 g_OQ[(DQTOT/16) * (SEQ/16) * 32];

// ---------------- helpers ----------------
__device__ __forceinline__ void bsplit2(float x0, float x1, uint32_t& hi, uint32_t& lo) {
    __nv_bfloat162 h = __floats2bfloat162_rn(x0, x1);
    float r0 = x0 - __bfloat162float(h.x);
    float r1 = x1 - __bfloat162float(h.y);
    __nv_bfloat162 l = __floats2bfloat162_rn(r0, r1);
    hi = *(uint32_t*)&h; lo = *(uint32_t*)&l;
}
__device__ __forceinline__ uint32_t h2pack(float a, float b) {
    __half2 h = __floats2half2_rn(a, b);
    return *(uint32_t*)&h;
}
__device__ __forceinline__ uint32_t s8x4(float a, float b, float c, float d, float inv) {
    int ia = max(-127, min(127, __float2int_rn(a * inv)));
    int ib = max(-127, min(127, __float2int_rn(b * inv)));
    int ic = max(-127, min(127, __float2int_rn(c * inv)));
    int id = max(-127, min(127, __float2int_rn(d * inv)));
    return (uint32_t)(ia & 0xff) | ((uint32_t)(ib & 0xff) << 8) |
           ((uint32_t)(ic & 0xff) << 16) | ((uint32_t)(id & 0xff) << 24);
}
__device__ __forceinline__ void mma16b(float* c, const uint32_t* a, const uint32_t* b) {
    asm volatile("mma.sync.aligned.m16n8k16.row.col.f32.bf16.bf16.f32 "
        "{%0,%1,%2,%3}, {%4,%5,%6,%7}, {%8,%9}, {%0,%1,%2,%3};\n"
        : "+f"(c[0]), "+f"(c[1]), "+f"(c[2]), "+f"(c[3])
        : "r"(a[0]), "r"(a[1]), "r"(a[2]), "r"(a[3]), "r"(b[0]), "r"(b[1]));
}
__device__ __forceinline__ void mma16h(float* c, const uint32_t* a, const uint32_t* b) {
    asm volatile("mma.sync.aligned.m16n8k16.row.col.f32.f16.f16.f32 "
        "{%0,%1,%2,%3}, {%4,%5,%6,%7}, {%8,%9}, {%0,%1,%2,%3};\n"
        : "+f"(c[0]), "+f"(c[1]), "+f"(c[2]), "+f"(c[3])
        : "r"(a[0]), "r"(a[1]), "r"(a[2]), "r"(a[3]), "r"(b[0]), "r"(b[1]));
}
__device__ __forceinline__ void mma_s8(int* c, const uint32_t* a, const uint32_t* b) {
    asm volatile("mma.sync.aligned.m16n8k32.row.col.s32.s8.s8.s32 "
        "{%0,%1,%2,%3}, {%4,%5,%6,%7}, {%8,%9}, {%0,%1,%2,%3};\n"
        : "+r"(c[0]), "+r"(c[1]), "+r"(c[2]), "+r"(c[3])
        : "r"(a[0]), "r"(a[1]), "r"(a[2]), "r"(a[3]), "r"(b[0]), "r"(b[1]));
}
__device__ __forceinline__ void cp16(uint32_t dst, const void* src) {
    asm volatile("cp.async.ca.shared.global [%0], [%1], 16;\n" :: "r"(dst), "l"(src));
}
__device__ __forceinline__ void cp_commit() { asm volatile("cp.async.commit_group;\n"); }
__device__ __forceinline__ void cp_wait0()  { asm volatile("cp.async.wait_group 0;\n"); }
__device__ __forceinline__ void cp_wait1()  { asm volatile("cp.async.wait_group 1;\n"); }

// ---------------- prep kernels ----------------
__global__ void prep_XQ(const float* __restrict__ X,
                        uint4* __restrict__ XhiQ, uint4* __restrict__ XloQ,
                        uint4* __restrict__ XhQ)
{
    int id  = blockIdx.x * 256 + threadIdx.x;
    int tig = id & 3, gid = (id >> 2) & 7, rg = (id >> 5) & (SEQ/16 - 1), c = id >> 13;
    const float* p0 = X + (size_t)(rg * 16 + gid) * HID + c * 16 + 2 * tig;
    const float* p1 = p0 + (size_t)8 * HID;
    float2 a0 = *(const float2*)p0, a1 = *(const float2*)p1;
    float2 a2 = *(const float2*)(p0 + 8), a3 = *(const float2*)(p1 + 8);
    uint32_t h0,l0,h1,l1,h2_,l2,h3,l3;
    bsplit2(a0.x, a0.y, h0, l0);
    bsplit2(a1.x, a1.y, h1, l1);
    bsplit2(a2.x, a2.y, h2_, l2);
    bsplit2(a3.x, a3.y, h3, l3);
    XhiQ[id] = make_uint4(h0, h1, h2_, h3);
    XloQ[id] = make_uint4(l0, l1, l2, l3);
    XhQ[id]  = make_uint4(h2pack(a0.x, a0.y), h2pack(a1.x, a1.y),
                          h2pack(a2.x, a2.y), h2pack(a3.x, a3.y));
}
// X -> s8 a-frags for k32 mma
__global__ void prep_X8(const float* __restrict__ X,
                        uint4* __restrict__ X8h, uint4* __restrict__ X8l)
{
    int id  = blockIdx.x * 256 + threadIdx.x;
    int tig = id & 3, gid = (id >> 2) & 7, rg = (id >> 5) & (SEQ/16 - 1), c32 = id >> 13;
    int r0 = rg * 16 + gid, kb = c32 * 32 + tig * 4;
    uint32_t qh[4], ql[4];
#pragma unroll
    for (int p = 0; p < 4; p++) {
        int r = (p & 1) ? r0 + 8 : r0;
        int k = kb + ((p >> 1) ? 16 : 0);
        float4 x = *(const float4*)&X[(size_t)r * HID + k];
        float h0 = __bfloat162float(__float2bfloat16(x.x));
        float h1 = __bfloat162float(__float2bfloat16(x.y));
        float h2_ = __bfloat162float(__float2bfloat16(x.z));
        float h3 = __bfloat162float(__float2bfloat16(x.w));
        qh[p] = s8x4(h0, h1, h2_, h3, SXH_INV);
        ql[p] = s8x4(x.x - h0, x.y - h1, x.z - h2_, x.w - h3, SXL_INV);
    }
    X8h[id] = make_uint4(qh[0], qh[1], qh[2], qh[3]);
    X8l[id] = make_uint4(ql[0], ql[1], ql[2], ql[3]);
}
// Wq -> bf16-hi b-frag pairs
__global__ void prep_WqHi(const float* __restrict__ W, uint2* __restrict__ out)
{
    int id = blockIdx.x * 256 + threadIdx.x;
    int tg = id & 3, n = (id >> 2) & 4095, c = id >> 14;
    const float* Wp = W + (size_t)(16 * c + 2 * tg) * DQTOT + n;
    __nv_bfloat162 hA = __floats2bfloat162_rn(Wp[0], Wp[DQTOT]);
    __nv_bfloat162 hB = __floats2bfloat162_rn(Wp[(size_t)8*DQTOT], Wp[(size_t)9*DQTOT]);
    out[id] = make_uint2(*(uint32_t*)&hA, *(uint32_t*)&hB);
}
// Wq -> s8 b-frags {b0hi,b1hi,b0lo,b1lo}
__global__ void prep_Wq8(const float* __restrict__ W, uint4* __restrict__ out)
{
    int id = blockIdx.x * 256 + threadIdx.x;
    int tg = id & 3, n = (id >> 2) & 4095, c32 = id >> 14;
    int kb = c32 * 32 + tg * 4;
    float h[8], l[8];
#pragma unroll
    for (int i = 0; i < 8; i++) {
        int k = kb + (i >> 2) * 16 + (i & 3);
        float wv = W[(size_t)k * DQTOT + n];
        h[i] = __bfloat162float(__float2bfloat16(wv));
        l[i] = wv - h[i];
    }
    out[id] = make_uint4(
        s8x4(h[0], h[1], h[2], h[3], SWH_INV), s8x4(h[4], h[5], h[6], h[7], SWH_INV),
        s8x4(l[0], l[1], l[2], l[3], SWL_INV), s8x4(l[4], l[5], l[6], l[7], SWL_INV));
}
__global__ void prep_W3(const float* __restrict__ W, uint4* __restrict__ out,
                        int N, int nMask, int nShift)
{
    int id = blockIdx.x * 256 + threadIdx.x;
    int tg = id & 3, n = (id >> 2) & nMask, c = id >> (2 + nShift);
    const float* Wp = W + (size_t)(16 * c + 2 * tg) * N + n;
    uint32_t hA, lA, hB, lB;
    bsplit2(Wp[0],           Wp[(size_t)N],    hA, lA);
    bsplit2(Wp[(size_t)8*N], Wp[(size_t)9*N], hB, lB);
    out[id] = make_uint4(hA, hB, lA, lB);
}
__global__ void prep_W2(const float* __restrict__ W, uint2* __restrict__ out,
                        int N, int nMask, int nShift)
{
    int id = blockIdx.x * 256 + threadIdx.x;
    int tg = id & 3, n = (id >> 2) & nMask, c = id >> (2 + nShift);
    const float* Wp = W + (size_t)(16 * c + 2 * tg) * N + n;
    out[id] = make_uint2(h2pack(Wp[0],           Wp[(size_t)N]),
                         h2pack(Wp[(size_t)8*N], Wp[(size_t)9*N]));
}

// ===========================================================================
// gemm_wq: hybrid bf16 + int8-compensated Wq GEMM with fused RoPE-Q epilogue.
// Tile 128x128 (N-tile = one head), BK=32, 256 threads, double buffered.
// smem bytes: Ahi[0,16384) X8h[16384,24576) X8l[24576,32768)
//             W8[32768,49152) BhiP[49152,65536); epi stage 128x132 f32.
// ===========================================================================
#define WQ_SMEM_BYTES 67584

__global__ __launch_bounds__(256, 1) void gemm_wq(
    const uint4* __restrict__ XhiQ,
    const uint4* __restrict__ X8h, const uint4* __restrict__ X8l,
    const uint2* __restrict__ WqHiP, const uint4* __restrict__ Wq8,
    const int* __restrict__ pos,
    __nv_bfloat16* __restrict__ Qhi, __nv_bfloat16* __restrict__ Qlo)
{
    extern __shared__ uint32_t smq[];
    const uint32_t smBase = (uint32_t)__cvta_generic_to_shared(smq);

    const int tid = threadIdx.x, lane = tid & 31, w = tid >> 5;
    const int wm = w >> 2, wn = w & 3;
    const int hb = blockIdx.x;
    const int m0 = blockIdx.y * 128;
    const int n0 = hb * 128;
    const int gid = lane >> 2, tig = lane & 3;
    const int rg0 = m0 >> 4;

    float c[4][4][4];
    int  c2[4][4][4];
#pragma unroll
    for (int mt = 0; mt < 4; mt++)
#pragma unroll
        for (int nt = 0; nt < 4; nt++)
#pragma unroll
            for (int q = 0; q < 4; q++) { c[mt][nt][q] = 0.f; c2[mt][nt][q] = 0; }

#define WQ_LOAD(t, buf) do {                                                   \
    _Pragma("unroll")                                                          \
    for (int l = 0; l < 2; l++) {                                              \
        int task = tid + l * 256;                                              \
        int ck = task >> 8, rg = (task >> 5) & 7, ln = task & 31;              \
        cp16(smBase + ((buf) * 512 + ck * 256 + rg * 32 + ln) * 16,            \
             XhiQ + ((size_t)((t) * 2 + ck) * 256 + rg0 + rg) * 32 + ln);      \
    }                                                                          \
    {                                                                          \
        int rg = tid >> 5, ln = tid & 31;                                      \
        cp16(smBase + 16384 + ((buf) * 256 + rg * 32 + ln) * 16,               \
             X8h + ((size_t)(t) * 256 + rg0 + rg) * 32 + ln);                  \
        cp16(smBase + 24576 + ((buf) * 256 + rg * 32 + ln) * 16,               \
             X8l + ((size_t)(t) * 256 + rg0 + rg) * 32 + ln);                  \
    }                                                                          \
    _Pragma("unroll")                                                          \
    for (int l = 0; l < 2; l++) {                                              \
        int task = tid + l * 256;                                              \
        int n = task >> 2, tg = task & 3;                                      \
        cp16(smBase + 32768 + ((buf) * 512 + n * 4 + tg) * 16,                 \
             Wq8 + ((size_t)(t) * DQTOT + n0 + n) * 4 + tg);                   \
    }                                                                          \
    _Pragma("unroll")                                                          \
    for (int l = 0; l < 2; l++) {                                              \
        int task = tid + l * 256;                                              \
        int ck = task >> 8, n = (task >> 1) & 127, hf = task & 1;              \
        cp16(smBase + 49152 + ((buf) * 1024 + (ck * 128 + n) * 4 + hf * 2) * 8,\
             WqHiP + ((size_t)((t) * 2 + ck) * DQTOT + n0 + n) * 4 + hf * 2);  \
    }                                                                          \
    cp_commit();                                                               \
} while (0)

    const uint4* AhiS = (const uint4*)smq;
    const uint4* X8hS = (const uint4*)(smq + 4096);
    const uint4* X8lS = (const uint4*)(smq + 6144);
    const uint4* W8S  = (const uint4*)(smq + 8192);
    const uint2* BhS  = (const uint2*)(smq + 12288);

    const int NT = HID / 32;
    WQ_LOAD(0, 0);

    for (int t = 0; t < NT; t++) {
        cp_wait0();
        __syncthreads();
        if (t + 1 < NT) WQ_LOAD(t + 1, (t + 1) & 1);
        const int buf = t & 1;

        // int8 cross terms (one k32 per chunk)
        uint32_t a8h[4][4], a8l[4][4];
#pragma unroll
        for (int mt = 0; mt < 4; mt++) {
            uint4 vh = X8hS[buf * 256 + (wm * 4 + mt) * 32 + lane];
            a8h[mt][0] = vh.x; a8h[mt][1] = vh.y; a8h[mt][2] = vh.z; a8h[mt][3] = vh.w;
            uint4 vl = X8lS[buf * 256 + (wm * 4 + mt) * 32 + lane];
            a8l[mt][0] = vl.x; a8l[mt][1] = vl.y; a8l[mt][2] = vl.z; a8l[mt][3] = vl.w;
        }
#pragma unroll
        for (int nt = 0; nt < 4; nt++) {
            uint4 w8 = W8S[buf * 512 + (wn * 32 + nt * 8 + gid) * 4 + tig];
            uint32_t bh8[2] = { w8.x, w8.y };
            uint32_t bl8[2] = { w8.z, w8.w };
#pragma unroll
            for (int mt = 0; mt < 4; mt++) {
                mma_s8(c2[mt][nt], a8l[mt], bh8);
                mma_s8(c2[mt][nt], a8h[mt], bl8);
            }
        }
        // bf16 main term (two k16 halves)
#pragma unroll
        for (int ck = 0; ck < 2; ck++) {
            uint32_t ahi[4][4];
#pragma unroll
            for (int mt = 0; mt < 4; mt++) {
                uint4 va = AhiS[buf * 512 + ck * 256 + (wm * 4 + mt) * 32 + lane];
                ahi[mt][0] = va.x; ahi[mt][1] = va.y; ahi[mt][2] = va.z; ahi[mt][3] = va.w;
            }
#pragma unroll
            for (int nt = 0; nt < 4; nt++) {
                uint2 bu = BhS[buf * 1024 + (ck * 128 + wn * 32 + nt * 8 + gid) * 4 + tig];
                uint32_t b[2] = { bu.x, bu.y };
#pragma unroll
                for (int mt = 0; mt < 4; mt++)
                    mma16b(c[mt][nt], ahi[mt], b);
            }
        }
    }

    // epilogue: merge cross terms, stage, RoPE-Q, bf16 split
    __syncthreads();
    float* stage = (float*)smq;   // [128][132]
#pragma unroll
    for (int mt = 0; mt < 4; mt++)
#pragma unroll
        for (int nt = 0; nt < 4; nt++) {
            int row = wm * 64 + mt * 16 + gid;
            int col = wn * 32 + nt * 8 + 2 * tig;
            *(float2*)&stage[row * 132 + col] = make_float2(
                c[mt][nt][0] + (float)c2[mt][nt][0] * CSCALE,
                c[mt][nt][1] + (float)c2[mt][nt][1] * CSCALE);
            *(float2*)&stage[(row + 8) * 132 + col] = make_float2(
                c[mt][nt][2] + (float)c2[mt][nt][2] * CSCALE,
                c[mt][nt][3] + (float)c2[mt][nt][3] * CSCALE);
        }
    __syncthreads();
    {
        const float SC = 0.08838834764831845f;
        const int d  = tid & 63;
        const int rb = tid >> 6;
        const float inv = powf(10000.0f, -(float)d / 64.0f);
#pragma unroll 4
        for (int i = 0; i < 32; i++) {
            int r = rb + i * 4;
            int s = m0 + r;
            float p = (float)pos[s];
            float sn, cs; sincosf(p * inv, &sn, &cs);
            float x1 = stage[r * 132 + d];
            float x2 = stage[r * 132 + d + 64];
            float o1 = (x1 * cs - x2 * sn) * SC;
            float o2 = (x2 * cs + x1 * sn) * SC;
            size_t idx = (size_t)s * DQTOT + hb * DH;
            __nv_bfloat16 h1 = __float2bfloat16(o1);
            __nv_bfloat16 h2v = __float2bfloat16(o2);
            Qhi[idx + d]      = h1;
            Qlo[idx + d]      = __float2bfloat16(o1 - __bfloat162float(h1));
            Qhi[idx + d + 64] = h2v;
            Qlo[idx + d + 64] = __float2bfloat16(o2 - __bfloat162float(h2v));
        }
    }
}

// ===========================================================================
// gemm_bf3q: bf16x3 GEMM with fused RoPE-K epilogue (Wk path, R12 EPI=2)
// ===========================================================================
#define G3Q_SMEM_BYTES 67584

__global__ __launch_bounds__(256, 2) void gemm_bf3q(
    const uint4* __restrict__ AhiQ, const uint4* __restrict__ AloQ,
    const uint4* __restrict__ Bq, const int* __restrict__ pos,
    uint4* __restrict__ KP, int N)
{
    extern __shared__ uint32_t smq[];
    const uint32_t smBase = (uint32_t)__cvta_generic_to_shared(smq);

    const int tid = threadIdx.x, lane = tid & 31, w = tid >> 5;
    const int wm = w >> 2, wn = w & 3;
    const int hb = blockIdx.x;
    const int m0 = blockIdx.y * 128;
    const int n0 = hb * 128;
    const int gid = lane >> 2, tig = lane & 3;
    const int rg0 = m0 >> 4;

    float c[4][4][4];
#pragma unroll
    for (int mt = 0; mt < 4; mt++)
#pragma unroll
        for (int nt = 0; nt < 4; nt++)
#pragma unroll
            for (int q = 0; q < 4; q++) c[mt][nt][q] = 0.f;

#define G3Q_LOAD(t, buf) do {                                                  \
    _Pragma("unroll")                                                          \
    for (int l = 0; l < 2; l++) {                                              \
        int task = tid + l * 256;                                              \
        int ck = task >> 8, rg = (task >> 5) & 7, ln = task & 31;              \
        size_t src = ((size_t)((t) * 2 + ck) * 256 + rg0 + rg) * 32 + ln;      \
        uint32_t dst = ((buf) * 512 + ck * 256 + rg * 32 + ln) * 16;           \
        cp16(smBase + dst,         AhiQ + src);                                \
        cp16(smBase + 16384 + dst, AloQ + src);                                \
    }                                                                          \
    _Pragma("unroll")                                                          \
    for (int l = 0; l < 4; l++) {                                              \
        int task = tid + l * 256;                                              \
        int ck = task >> 9, n = (task >> 2) & 127, tg = task & 3;              \
        cp16(smBase + 32768 + ((buf) * 1024 + (ck * 128 + n) * 4 + tg) * 16,   \
             Bq + ((size_t)((t) * 2 + ck) * N + n0 + n) * 4 + tg);             \
    }                                                                          \
    cp_commit();                                                               \
} while (0)

    const uint4* AhiS = (const uint4*)smq;
    const uint4* AloS = (const uint4*)(smq + 4096);
    const uint4* BqS  = (const uint4*)(smq + 8192);

    const int NT = HID / 32;
    G3Q_LOAD(0, 0);

    for (int t = 0; t < NT; t++) {
        cp_wait0();
        __syncthreads();
        if (t + 1 < NT) G3Q_LOAD(t + 1, (t + 1) & 1);
        const int buf = t & 1;
#pragma unroll
        for (int ck = 0; ck < 2; ck++) {
            uint32_t ahi[4][4], alo[4][4];
#pragma unroll
            for (int mt = 0; mt < 4; mt++) {
                uint4 va = AhiS[buf * 512 + ck * 256 + (wm * 4 + mt) * 32 + lane];
                ahi[mt][0] = va.x; ahi[mt][1] = va.y; ahi[mt][2] = va.z; ahi[mt][3] = va.w;
                uint4 vl = AloS[buf * 512 + ck * 256 + (wm * 4 + mt) * 32 + lane];
                alo[mt][0] = vl.x; alo[mt][1] = vl.y; alo[mt][2] = vl.z; alo[mt][3] = vl.w;
            }
#pragma unroll
            for (int nt = 0; nt < 4; nt++) {
                uint4 bq = BqS[buf * 1024 + ck * 512 + (wn * 32 + nt * 8 + gid) * 4 + tig];
                uint32_t bhi[2] = { bq.x, bq.y };
                uint32_t blo[2] = { bq.z, bq.w };
#pragma unroll
                for (int mt = 0; mt < 4; mt++) {
                    mma16b(c[mt][nt], ahi[mt], bhi);
                    mma16b(c[mt][nt], ahi[mt], blo);
                    mma16b(c[mt][nt], alo[mt], bhi);
                }
            }
        }
    }

    __syncthreads();
    float* stage = (float*)smq;
#pragma unroll
    for (int mt = 0; mt < 4; mt++)
#pragma unroll
        for (int nt = 0; nt < 4; nt++) {
            int row = wm * 64 + mt * 16 + gid;
            int col = wn * 32 + nt * 8 + 2 * tig;
            *(float2*)&stage[row * 132 + col] = make_float2(c[mt][nt][0], c[mt][nt][1]);
            *(float2*)&stage[(row + 8) * 132 + col] = make_float2(c[mt][nt][2], c[mt][nt][3]);
        }
    __syncthreads();
    {
        const int j  = tid & 31;
        const int rb = tid >> 5;
        const float inv0 = powf(10000.0f, -(float)(2 * j)     / 64.0f);
        const float inv1 = powf(10000.0f, -(float)(2 * j + 1) / 64.0f);
        const int cL = j >> 3, tg = j & 3, slot = (j >> 2) & 1;
#pragma unroll 4
        for (int i = 0; i < 16; i++) {
            int r = rb + i * 8;
            int s = m0 + r;
            float p = (float)pos[s];
            float s0, c0, s1, c1;
            sincosf(p * inv0, &s0, &c0);
            sincosf(p * inv1, &s1, &c1);
            float aL0 = stage[r * 132 + 2 * j],      aL1 = stage[r * 132 + 2 * j + 1];
            float aH0 = stage[r * 132 + 2 * j + 64], aH1 = stage[r * 132 + 2 * j + 65];
            float oL0 = aL0 * c0 - aH0 * s0;
            float oL1 = aL1 * c1 - aH1 * s1;
            float oH0 = aH0 * c0 + aL0 * s0;
            float oH1 = aH1 * c1 + aL1 * s1;
            uint32_t hL, lL, hH, lH;
            bsplit2(oL0, oL1, hL, lL);
            bsplit2(oH0, oH1, hH, lH);
            uint32_t* q1 = (uint32_t*)&KP[((size_t)(hb * 8 + cL) * SEQ + s) * 4 + tg];
            q1[slot] = hL; q1[2 + slot] = lL;
            uint32_t* q2 = (uint32_t*)&KP[((size_t)(hb * 8 + 4 + cL) * SEQ + s) * 4 + tg];
            q2[slot] = hH; q2[2 + slot] = lH;
        }
    }
}

// ===========================================================================
// gemm_f16q<VPACK>: fp16 GEMM (unchanged)
// ===========================================================================
#define F16Q_SMEM_BYTES (8448 * 4)

template<bool VPACK>
__global__ __launch_bounds__(256, 2) void gemm_f16q(
    const uint4* __restrict__ AQ, const uint2* __restrict__ B2,
    float* __restrict__ C, uint2* __restrict__ VP,
    int M, int N, int K)
{
    extern __shared__ uint32_t smq[];
    const uint32_t smBase = (uint32_t)__cvta_generic_to_shared(smq);
    const int tid = threadIdx.x, lane = tid & 31, w = tid >> 5;
    const int wm = w >> 2, wn = w & 3;
    const int m0 = blockIdx.y * 128, n0 = blockIdx.x * 128;
    const int gid = lane >> 2, tig = lane & 3;
    const int Mg = M >> 4, rg0 = m0 >> 4;

    float c[4][4][4];
#pragma unroll
    for (int mt = 0; mt < 4; mt++)
#pragma unroll
        for (int nt = 0; nt < 4; nt++)
#pragma unroll
            for (int q = 0; q < 4; q++) c[mt][nt][q] = 0.f;

#define F16Q_LOAD(t, buf) do {                                                 \
    _Pragma("unroll")                                                          \
    for (int l = 0; l < 2; l++) {                                              \
        int task = tid + l * 256;                                              \
        int ck = task >> 8, rg = (task >> 5) & 7, ln = task & 31;              \
        cp16(smBase + ((buf) * 512 + ck * 256 + rg * 32 + ln) * 16,            \
             AQ + ((size_t)((t) * 2 + ck) * Mg + rg0 + rg) * 32 + ln);         \
    }                                                                          \
    _Pragma("unroll")                                                          \
    for (int l = 0; l < 2; l++) {                                              \
        int task = tid + l * 256;                                              \
        int ck = task >> 8, n = (task >> 1) & 127, hf = task & 1;              \
        cp16(smBase + 16384 + ((buf) * 1024 + (ck * 128 + n) * 4 + hf * 2) * 8,\
             B2 + ((size_t)((t) * 2 + ck) * N + n0 + n) * 4 + hf * 2);         \
    }                                                                          \
    cp_commit();                                                               \
} while (0)

    const uint4* AQS = (const uint4*)smq;
    const uint2* B2S = (const uint2*)(smq + 4096);
    const int NT = K / 32;
    F16Q_LOAD(0, 0);
    for (int t = 0; t < NT; t++) {
        cp_wait0();
        __syncthreads();
        if (t + 1 < NT) F16Q_LOAD(t + 1, (t + 1) & 1);
        const int buf = t & 1;
#pragma unroll
        for (int ck = 0; ck < 2; ck++) {
            uint32_t a[4][4];
#pragma unroll
            for (int mt = 0; mt < 4; mt++) {
                uint4 va = AQS[buf * 512 + ck * 256 + (wm * 4 + mt) * 32 + lane];
                a[mt][0] = va.x; a[mt][1] = va.y; a[mt][2] = va.z; a[mt][3] = va.w;
            }
#pragma unroll
            for (int nt = 0; nt < 4; nt++) {
                int nc = wn * 32 + nt * 8 + gid;
                uint2 bu = B2S[buf * 1024 + ck * 512 + nc * 4 + tig];
                uint32_t b[2] = { bu.x, bu.y };
#pragma unroll
                for (int mt = 0; mt < 4; mt++)
                    mma16h(c[mt][nt], a[mt], b);
            }
        }
    }

    if (!VPACK) {
#pragma unroll
        for (int mt = 0; mt < 4; mt++)
#pragma unroll
            for (int nt = 0; nt < 4; nt++) {
                int row = m0 + wm * 64 + mt * 16 + gid;
                int col = n0 + wn * 32 + nt * 8 + 2 * tig;
                *(float2*)&C[(size_t)row * N + col] = make_float2(c[mt][nt][0], c[mt][nt][1]);
                *(float2*)&C[(size_t)(row + 8) * N + col] = make_float2(c[mt][nt][2], c[mt][nt][3]);
            }
    } else {
        __syncthreads();
        uint32_t* stage = smq;
#pragma unroll
        for (int mt = 0; mt < 4; mt++)
#pragma unroll
            for (int nt = 0; nt < 4; nt++) {
                int rm = wm * 64 + mt * 16 + gid;
                int cu = wn * 16 + nt * 4 + tig;
                stage[rm * 66 + cu]       = h2pack(c[mt][nt][0], c[mt][nt][1]);
                stage[(rm + 8) * 66 + cu] = h2pack(c[mt][nt][2], c[mt][nt][3]);
            }
        __syncthreads();
        const __half* stageH = (const __half*)stage;
        int hk = n0 >> 7, jg0 = m0 >> 4;
#pragma unroll
        for (int i = 0; i < 16; i++) {
            int task = tid + i * 256;
            int d = task >> 5, jl = (task >> 2) & 7, tg = task & 3;
            int s = 16 * jl + 2 * tg;
            __half2 pA = __halves2half2(stageH[s * 132 + d],       stageH[(s + 1) * 132 + d]);
            __half2 pB = __halves2half2(stageH[(s + 8) * 132 + d], stageH[(s + 9) * 132 + d]);
            VP[((size_t)(hk * 128 + d) * 256 + jg0 + jl) * 4 + tg] =
                make_uint2(*(uint32_t*)&pA, *(uint32_t*)&pB);
        }
    }
}

// ===========================================================================
// flash_mma: unchanged from R8
// ===========================================================================
#define FL_SMEM_BYTES (26624 * 4)

__global__ __launch_bounds__(256, 1) void flash_mma(
    const uint32_t* __restrict__ Qhi, const uint32_t* __restrict__ Qlo,
    const uint4* __restrict__ KP, const uint2* __restrict__ VP,
    uint4* __restrict__ OQ)
{
    extern __shared__ uint32_t sm[];
    const uint32_t smBase = (uint32_t)__cvta_generic_to_shared(sm);
    const int qb = (gridDim.x - 1) - blockIdx.x;
    const int h = blockIdx.y, hk = h >> 3;
    const int tid = threadIdx.x, lane = tid & 31, w = tid >> 5;
    const int gid = lane >> 2, tig = lane & 3;
    const int r0 = w * 16 + gid, r0g = qb * 128 + r0;

    uint32_t qhi[8][4], qlo[8][4];
#pragma unroll
    for (int c = 0; c < 8; c++) {
        size_t i0 = (size_t)r0g * 2048 + h * 64 + c * 8 + tig;
        qhi[c][0] = Qhi[i0];     qhi[c][1] = Qhi[i0 + 8 * 2048];
        qhi[c][2] = Qhi[i0 + 4]; qhi[c][3] = Qhi[i0 + 8 * 2048 + 4];
        qlo[c][0] = Qlo[i0];     qlo[c][1] = Qlo[i0 + 8 * 2048];
        qlo[c][2] = Qlo[i0 + 4]; qlo[c][3] = Qlo[i0 + 8 * 2048 + 4];
    }

#define FL_ISSUE(kb, buf) do {                                                 \
    _Pragma("unroll")                                                          \
    for (int l = 0; l < 8; l++) {                                              \
        int task = tid + l * 256;                                              \
        int cc = task >> 8, ss = (task >> 2) & 63, tg = task & 3;              \
        cp16(smBase + ((buf) * 8192 + ((cc * 64 + ss) * 4 + tg) * 4) * 4,      \
             KP + ((size_t)(hk * 8 + cc) * SEQ + (kb) * 64 + ss) * 4 + tg);    \
    }                                                                          \
    _Pragma("unroll")                                                          \
    for (int l = 0; l < 4; l++) {                                              \
        int task = tid + l * 256;                                              \
        int dd = task >> 3, jj = (task >> 1) & 3, hf = task & 1;               \
        cp16(smBase + (16384 + (buf) * 5120 + (dd * 20 + jj * 4 + hf * 2) * 2) * 4, \
             VP + ((size_t)(hk * 128 + dd) * 256 + (kb) * 4 + jj) * 4 + hf * 2); \
    }                                                                          \
    cp_commit();                                                               \
} while (0)

    float l_[2] = { 0.f, 0.f };
    float o[16][4];
#pragma unroll
    for (int nt = 0; nt < 16; nt++)
#pragma unroll
        for (int q = 0; q < 4; q++) o[nt][q] = 0.f;

    const int kbmax = 2 * qb + 1;
    FL_ISSUE(0, 0);

    for (int kb = 0; kb <= kbmax; kb++) {
        __syncthreads();
        if (kb < kbmax) { FL_ISSUE(kb + 1, (kb + 1) & 1); cp_wait1(); }
        else             cp_wait0();
        __syncthreads();

        const int buf = kb & 1;
        const uint4* Ksp = (const uint4*)sm + buf * 2048;
        const uint2* Vsp = (const uint2*)(sm + 16384) + buf * 2560;

        float s[8][4];
#pragma unroll
        for (int nt = 0; nt < 8; nt++)
#pragma unroll
            for (int q = 0; q < 4; q++) s[nt][q] = 0.f;
#pragma unroll
        for (int c = 0; c < 8; c++) {
            const uint4* kbase = Ksp + c * 256 + tig;
#pragma unroll
            for (int nt = 0; nt < 8; nt++) {
                uint4 kf = kbase[(nt * 8 + gid) * 4];
                uint32_t bhi[2] = { kf.x, kf.y };
                uint32_t blo[2] = { kf.z, kf.w };
                mma16b(s[nt], qhi[c], bhi);
                mma16b(s[nt], qhi[c], blo);
                mma16b(s[nt], qlo[c], bhi);
            }
        }
        if (kb >= 2 * qb) {
#pragma unroll
            for (int nt = 0; nt < 8; nt++) {
                int col = kb * 64 + nt * 8 + 2 * tig;
                if (col     > r0g)     s[nt][0] = -1e30f;
                if (col + 1 > r0g)     s[nt][1] = -1e30f;
                if (col     > r0g + 8) s[nt][2] = -1e30f;
                if (col + 1 > r0g + 8) s[nt][3] = -1e30f;
            }
        }
        float rs0 = 0.f, rs1 = 0.f;
        uint32_t pa[4][4];
#pragma unroll
        for (int j = 0; j < 4; j++) {
            float e00 = __expf(s[2*j][0]),   e01 = __expf(s[2*j][1]);
            float e02 = __expf(s[2*j][2]),   e03 = __expf(s[2*j][3]);
            float e10 = __expf(s[2*j+1][0]), e11 = __expf(s[2*j+1][1]);
            float e12 = __expf(s[2*j+1][2]), e13 = __expf(s[2*j+1][3]);
            rs0 += (e00 + e01) + (e10 + e11);
            rs1 += (e02 + e03) + (e12 + e13);
            pa[j][0] = h2pack(e00, e01); pa[j][1] = h2pack(e02, e03);
            pa[j][2] = h2pack(e10, e11); pa[j][3] = h2pack(e12, e13);
        }
        rs0 += __shfl_xor_sync(0xffffffffu, rs0, 1);
        rs0 += __shfl_xor_sync(0xffffffffu, rs0, 2);
        rs1 += __shfl_xor_sync(0xffffffffu, rs1, 1);
        rs1 += __shfl_xor_sync(0xffffffffu, rs1, 2);
        l_[0] += rs0; l_[1] += rs1;
#pragma unroll
        for (int j = 0; j < 4; j++) {
#pragma unroll
            for (int nt = 0; nt < 16; nt++) {
                uint2 vv = Vsp[(nt * 8 + gid) * 20 + j * 4 + tig];
                uint32_t b[2] = { vv.x, vv.y };
                mma16h(o[nt], pa[j], b);
            }
        }
    }
    {
        const float il0 = 1.0f / l_[0], il1 = 1.0f / l_[1];
        const int rgO = qb * 8 + w;
#pragma unroll
        for (int j = 0; j < 8; j++) {
            int c = h * 8 + j;
            uint4 u;
            u.x = h2pack(o[2*j][0]   * il0, o[2*j][1]   * il0);
            u.y = h2pack(o[2*j][2]   * il1, o[2*j][3]   * il1);
            u.z = h2pack(o[2*j+1][0] * il0, o[2*j+1][1] * il0);
            u.w = h2pack(o[2*j+1][2] * il1, o[2*j+1][3] * il1);
            OQ[((size_t)(c * 256 + rgO) * 8 + gid) * 4 + tig] = u;
        }
    }
}

// ---------------- launch ----------------
extern "C" void kernel_launch(void* const* d_in, const int* in_sizes, int n_in,
                              void* d_out, int out_size)
{
    const float* X  = (const float*)d_in[0];
    const float* Wq = (const float*)d_in[1];
    const float* Wk = (const float*)d_in[2];
    const float* Wv = (const float*)d_in[3];
    const float* Wo = (const float*)d_in[4];
    const int*  pos = (const int*)d_in[5];
    float* out = (float*)d_out;

    uint4 *XhiQ, *XloQ, *XhQ, *X8h, *X8l, *Wq8, *WkT, *KPp, *OQp;
    uint2 *WqHiP, *WvT, *WoT, *VPp;
    __nv_bfloat16 *Qhi, *Qlo;
    cudaGetSymbolAddress((void**)&XhiQ,  g_XhiQ);
    cudaGetSymbolAddress((void**)&XloQ,  g_XloQ);
    cudaGetSymbolAddress((void**)&XhQ,   g_XhQ);
    cudaGetSymbolAddress((void**)&X8h,   g_X8h);
    cudaGetSymbolAddress((void**)&X8l,   g_X8l);
    cudaGetSymbolAddress((void**)&WqHiP, g_WqHiP);
    cudaGetSymbolAddress((void**)&Wq8,   g_Wq8);
    cudaGetSymbolAddress((void**)&WkT,   g_WkT);
    cudaGetSymbolAddress((void**)&WvT,   g_WvT);
    cudaGetSymbolAddress((void**)&WoT,   g_WoT);
    cudaGetSymbolAddress((void**)&Qhi,   g_Qhi);
    cudaGetSymbolAddress((void**)&Qlo,   g_Qlo);
    cudaGetSymbolAddress((void**)&KPp,   g_KP);
    cudaGetSymbolAddress((void**)&VPp,   g_VP);
    cudaGetSymbolAddress((void**)&OQp,   g_OQ);

    cudaFuncSetAttribute(gemm_wq, cudaFuncAttributeMaxDynamicSharedMemorySize, WQ_SMEM_BYTES);
    cudaFuncSetAttribute(gemm_bf3q, cudaFuncAttributeMaxDynamicSharedMemorySize, G3Q_SMEM_BYTES);
    cudaFuncSetAttribute(gemm_f16q<false>, cudaFuncAttributeMaxDynamicSharedMemorySize, F16Q_SMEM_BYTES);
    cudaFuncSetAttribute(gemm_f16q<true>, cudaFuncAttributeMaxDynamicSharedMemorySize, F16Q_SMEM_BYTES);
    cudaFuncSetAttribute(flash_mma, cudaFuncAttributeMaxDynamicSharedMemorySize, FL_SMEM_BYTES);

    // prep
    prep_XQ<<<(HID/16) * (SEQ/16) * 32 / 256, 256>>>(X, XhiQ, XloQ, XhQ);
    prep_X8<<<(HID/32) * (SEQ/16) * 32 / 256, 256>>>(X, X8h, X8l);
    prep_WqHi<<<(HID/16) * DQTOT * 4 / 256, 256>>>(Wq, WqHiP);
    prep_Wq8<<<(HID/32) * DQTOT * 4 / 256, 256>>>(Wq, Wq8);
    prep_W3<<<(HID/16) * DKVTOT * 4 / 256, 256>>>(Wk, WkT, DKVTOT, DKVTOT - 1, 9);
    prep_W2<<<(HID/16) * DKVTOT * 4 / 256, 256>>>(Wv, WvT, DKVTOT, DKVTOT - 1, 9);
    prep_W2<<<(DQTOT/16) * HID * 4 / 256, 256>>>(Wo, WoT, HID, HID - 1, 11);

    // projections with fused RoPE
    gemm_wq<<<dim3(NHQ, SEQ / 128), 256, WQ_SMEM_BYTES>>>(
        XhiQ, X8h, X8l, WqHiP, Wq8, pos, Qhi, Qlo);
    gemm_bf3q<<<dim3(NHKV, SEQ / 128), 256, G3Q_SMEM_BYTES>>>(
        XhiQ, XloQ, WkT, pos, KPp, DKVTOT);
    gemm_f16q<true><<<dim3(DKVTOT / 128, SEQ / 128), 256, F16Q_SMEM_BYTES>>>(
        XhQ, WvT, nullptr, VPp, SEQ, DKVTOT, HID);

    // attention
    flash_mma<<<dim3(SEQ / 128, NHQ), 256, FL_SMEM_BYTES>>>(
        (const uint32_t*)Qhi, (const uint32_t*)Qlo, KPp, VPp, OQp);

    // output projection
    gemm_f16q<false><<<dim3(HID / 128, SEQ / 128), 256, F16Q_SMEM_BYTES>>>(
        OQp, WoT, out, nullptr, SEQ, HID, DQTOT);
}

// round 15
// speedup vs baseline: 1.6035x; 1.6035x over previous
#include <cuda_runtime.h>
#include <cuda_fp16.h>
#include <math.h>
#include <stdint.h>

#define SEQ   4096
#define HID   2048
#define NHQ   32
#define NHKV  4
#define DH    128
#define DQTOT (NHQ*DH)
#define DKVTOT (NHKV*DH)

// ---------------- scratch ----------------
__device__ uint4 g_XhQ [(HID/16) * (SEQ/16) * 32];   // X fp16 a-frag quads, 16MB
__device__ uint2 g_WqB[(HID/16) * DQTOT * 4];        // Wq fp16 b-frag pairs, 16MB
__device__ uint2 g_WkB[(HID/16) * DKVTOT * 4];       // 2MB
__device__ uint2 g_WvB[(HID/16) * DKVTOT * 4];       // 2MB
__device__ uint2 g_WoB[(DQTOT/16) * HID * 4];        // 16MB
__device__ uint32_t g_Qh[SEQ * DQTOT / 2];           // Q fp16 pairs row-major, 32MB
__device__ uint2 g_KP2[NHKV * 8 * SEQ * 4];          // K fp16 b-frag layout, 4MB
__device__ uint2 g_VP[NHKV * DH * (SEQ/16) * 4];     // V fp16 pair layout, 4MB
__device__ uint4 g_OQ[(DQTOT/16) * (SEQ/16) * 32];   // O fp16 a-frag quads, 32MB

// ---------------- helpers ----------------
__device__ __forceinline__ uint32_t h2pack(float a, float b) {
    __half2 h = __floats2half2_rn(a, b);
    return *(uint32_t*)&h;
}
__device__ __forceinline__ void mma16h(float* c, const uint32_t* a, const uint32_t* b) {
    asm volatile("mma.sync.aligned.m16n8k16.row.col.f32.f16.f16.f32 "
        "{%0,%1,%2,%3}, {%4,%5,%6,%7}, {%8,%9}, {%0,%1,%2,%3};\n"
        : "+f"(c[0]), "+f"(c[1]), "+f"(c[2]), "+f"(c[3])
        : "r"(a[0]), "r"(a[1]), "r"(a[2]), "r"(a[3]), "r"(b[0]), "r"(b[1]));
}
__device__ __forceinline__ void cp16(uint32_t dst, const void* src) {
    asm volatile("cp.async.ca.shared.global [%0], [%1], 16;\n" :: "r"(dst), "l"(src));
}
__device__ __forceinline__ void cp_commit() { asm volatile("cp.async.commit_group;\n"); }
__device__ __forceinline__ void cp_wait0()  { asm volatile("cp.async.wait_group 0;\n"); }
__device__ __forceinline__ void cp_wait1()  { asm volatile("cp.async.wait_group 1;\n"); }

// ---------------- prep kernels ----------------
// X -> fp16 a-frag quads
__global__ void prep_XQh(const float* __restrict__ X, uint4* __restrict__ XhQ)
{
    int id  = blockIdx.x * 256 + threadIdx.x;
    int tig = id & 3, gid = (id >> 2) & 7, rg = (id >> 5) & (SEQ/16 - 1), c = id >> 13;
    const float* p0 = X + (size_t)(rg * 16 + gid) * HID + c * 16 + 2 * tig;
    const float* p1 = p0 + (size_t)8 * HID;
    float2 a0 = *(const float2*)p0, a1 = *(const float2*)p1;
    float2 a2 = *(const float2*)(p0 + 8), a3 = *(const float2*)(p1 + 8);
    XhQ[id] = make_uint4(h2pack(a0.x, a0.y), h2pack(a1.x, a1.y),
                         h2pack(a2.x, a2.y), h2pack(a3.x, a3.y));
}
// W[K][N] -> fp16 b-frag pairs
__global__ void prep_W2(const float* __restrict__ W, uint2* __restrict__ out,
                        int N, int nMask, int nShift)
{
    int id = blockIdx.x * 256 + threadIdx.x;
    int tg = id & 3, n = (id >> 2) & nMask, c = id >> (2 + nShift);
    const float* Wp = W + (size_t)(16 * c + 2 * tg) * N + n;
    out[id] = make_uint2(h2pack(Wp[0],           Wp[(size_t)N]),
                         h2pack(Wp[(size_t)8*N], Wp[(size_t)9*N]));
}

// ===========================================================================
// gemm_f16q<EPI>: fp16 single-pass GEMM. Tile 128x128, BK=32, 256 thr, dbuf.
// EPI=0: f32 C (Wo).  EPI=1: fused RoPE-Q -> Qh fp16 pairs.
// EPI=2: fused RoPE-K -> KP2 b-frag layout.  EPI=3: V pack -> VP.
// ===========================================================================
#define F16Q_SMEM_BYTES 67584

template<int EPI>
__global__ __launch_bounds__(256, 2) void gemm_f16q(
    const uint4* __restrict__ AQ, const uint2* __restrict__ B2,
    const int* __restrict__ pos, float* __restrict__ C,
    uint2* __restrict__ VP, uint32_t* __restrict__ Qh, uint2* __restrict__ KP2,
    int M, int N, int K)
{
    extern __shared__ uint32_t smq[];
    const uint32_t smBase = (uint32_t)__cvta_generic_to_shared(smq);
    const int tid = threadIdx.x, lane = tid & 31, w = tid >> 5;
    const int wm = w >> 2, wn = w & 3;
    const int m0 = blockIdx.y * 128, n0 = blockIdx.x * 128;
    const int hb = blockIdx.x;
    const int gid = lane >> 2, tig = lane & 3;
    const int Mg = M >> 4, rg0 = m0 >> 4;

    float c[4][4][4];
#pragma unroll
    for (int mt = 0; mt < 4; mt++)
#pragma unroll
        for (int nt = 0; nt < 4; nt++)
#pragma unroll
            for (int q = 0; q < 4; q++) c[mt][nt][q] = 0.f;

#define F16Q_LOAD(t, buf) do {                                                 \
    _Pragma("unroll")                                                          \
    for (int l = 0; l < 2; l++) {                                              \
        int task = tid + l * 256;                                              \
        int ck = task >> 8, rg = (task >> 5) & 7, ln = task & 31;              \
        cp16(smBase + ((buf) * 512 + ck * 256 + rg * 32 + ln) * 16,            \
             AQ + ((size_t)((t) * 2 + ck) * Mg + rg0 + rg) * 32 + ln);         \
    }                                                                          \
    _Pragma("unroll")                                                          \
    for (int l = 0; l < 2; l++) {                                              \
        int task = tid + l * 256;                                              \
        int ck = task >> 8, n = (task >> 1) & 127, hf = task & 1;              \
        cp16(smBase + 16384 + ((buf) * 1024 + (ck * 128 + n) * 4 + hf * 2) * 8,\
             B2 + ((size_t)((t) * 2 + ck) * N + n0 + n) * 4 + hf * 2);         \
    }                                                                          \
    cp_commit();                                                               \
} while (0)

    const uint4* AQS = (const uint4*)smq;
    const uint2* B2S = (const uint2*)(smq + 4096);
    const int NT = K / 32;
    F16Q_LOAD(0, 0);
    for (int t = 0; t < NT; t++) {
        cp_wait0();
        __syncthreads();
        if (t + 1 < NT) F16Q_LOAD(t + 1, (t + 1) & 1);
        const int buf = t & 1;
#pragma unroll
        for (int ck = 0; ck < 2; ck++) {
            uint32_t a[4][4];
#pragma unroll
            for (int mt = 0; mt < 4; mt++) {
                uint4 va = AQS[buf * 512 + ck * 256 + (wm * 4 + mt) * 32 + lane];
                a[mt][0] = va.x; a[mt][1] = va.y; a[mt][2] = va.z; a[mt][3] = va.w;
            }
#pragma unroll
            for (int nt = 0; nt < 4; nt++) {
                int nc = wn * 32 + nt * 8 + gid;
                uint2 bu = B2S[buf * 1024 + ck * 512 + nc * 4 + tig];
                uint32_t b[2] = { bu.x, bu.y };
#pragma unroll
                for (int mt = 0; mt < 4; mt++)
                    mma16h(c[mt][nt], a[mt], b);
            }
        }
    }

    if (EPI == 0) {
#pragma unroll
        for (int mt = 0; mt < 4; mt++)
#pragma unroll
            for (int nt = 0; nt < 4; nt++) {
                int row = m0 + wm * 64 + mt * 16 + gid;
                int col = n0 + wn * 32 + nt * 8 + 2 * tig;
                *(float2*)&C[(size_t)row * N + col] = make_float2(c[mt][nt][0], c[mt][nt][1]);
                *(float2*)&C[(size_t)(row + 8) * N + col] = make_float2(c[mt][nt][2], c[mt][nt][3]);
            }
        return;
    }
    if (EPI == 3) {
        __syncthreads();
        uint32_t* stg = smq;
#pragma unroll
        for (int mt = 0; mt < 4; mt++)
#pragma unroll
            for (int nt = 0; nt < 4; nt++) {
                int rm = wm * 64 + mt * 16 + gid;
                int cu = wn * 16 + nt * 4 + tig;
                stg[rm * 66 + cu]       = h2pack(c[mt][nt][0], c[mt][nt][1]);
                stg[(rm + 8) * 66 + cu] = h2pack(c[mt][nt][2], c[mt][nt][3]);
            }
        __syncthreads();
        const __half* sh = (const __half*)smq;
        int hk = n0 >> 7, jg0 = m0 >> 4;
#pragma unroll
        for (int i = 0; i < 16; i++) {
            int task = tid + i * 256;
            int d = task >> 5, jl = (task >> 2) & 7, tg = task & 3;
            int s = 16 * jl + 2 * tg;
            __half2 pA = __halves2half2(sh[s * 132 + d],       sh[(s + 1) * 132 + d]);
            __half2 pB = __halves2half2(sh[(s + 8) * 132 + d], sh[(s + 9) * 132 + d]);
            VP[((size_t)(hk * 128 + d) * 256 + jg0 + jl) * 4 + tg] =
                make_uint2(*(uint32_t*)&pA, *(uint32_t*)&pB);
        }
        return;
    }
    // EPI 1/2: stage f32 tile then fused RoPE
    __syncthreads();
    float* stage = (float*)smq;   // [128][132]
#pragma unroll
    for (int mt = 0; mt < 4; mt++)
#pragma unroll
        for (int nt = 0; nt < 4; nt++) {
            int row = wm * 64 + mt * 16 + gid;
            int col = wn * 32 + nt * 8 + 2 * tig;
            *(float2*)&stage[row * 132 + col] = make_float2(c[mt][nt][0], c[mt][nt][1]);
            *(float2*)&stage[(row + 8) * 132 + col] = make_float2(c[mt][nt][2], c[mt][nt][3]);
        }
    __syncthreads();
    {
        const int j  = tid & 31;
        const int rb = tid >> 5;
        const float inv0 = powf(10000.0f, -(float)(2 * j)     / 64.0f);
        const float inv1 = powf(10000.0f, -(float)(2 * j + 1) / 64.0f);
        const float SC = (EPI == 1) ? 0.08838834764831845f : 1.0f;
        const int cL = j >> 3, tg = j & 3, slot = (j >> 2) & 1;
#pragma unroll 4
        for (int i = 0; i < 16; i++) {
            int r = rb + i * 8;
            int s = m0 + r;
            float p = (float)pos[s];
            float s0, c0, s1, c1;
            sincosf(p * inv0, &s0, &c0);
            sincosf(p * inv1, &s1, &c1);
            float xL0 = stage[r * 132 + 2 * j],      xL1 = stage[r * 132 + 2 * j + 1];
            float xH0 = stage[r * 132 + 2 * j + 64], xH1 = stage[r * 132 + 2 * j + 65];
            float oL0 = (xL0 * c0 - xH0 * s0) * SC;
            float oL1 = (xL1 * c1 - xH1 * s1) * SC;
            float oH0 = (xH0 * c0 + xL0 * s0) * SC;
            float oH1 = (xH1 * c1 + xL1 * s1) * SC;
            if (EPI == 1) {
                size_t base = (size_t)s * 2048 + hb * 64;
                Qh[base + j]      = h2pack(oL0, oL1);
                Qh[base + 32 + j] = h2pack(oH0, oH1);
            } else {
                ((uint32_t*)&KP2[((size_t)(hb * 8 + cL) * SEQ + s) * 4 + tg])[slot] =
                    h2pack(oL0, oL1);
                ((uint32_t*)&KP2[((size_t)(hb * 8 + 4 + cL) * SEQ + s) * 4 + tg])[slot] =
                    h2pack(oH0, oH1);
            }
        }
    }
}

// ===========================================================================
// flash_mma: 128 q-rows x 64 kv tiles, all-fp16 single-pass QK + PV.
// smem u32: K uint2[2][2048] @0 (8192), V uint2[2][2560] @8192 (10240)
// ===========================================================================
#define FL_SMEM_BYTES (18432 * 4)   // 73728

__global__ __launch_bounds__(256, 1) void flash_mma(
    const uint32_t* __restrict__ Qh,
    const uint2* __restrict__ KP2, const uint2* __restrict__ VP,
    uint4* __restrict__ OQ)
{
    extern __shared__ uint32_t sm[];
    const uint32_t smBase = (uint32_t)__cvta_generic_to_shared(sm);
    const int qb = (gridDim.x - 1) - blockIdx.x;
    const int h = blockIdx.y, hk = h >> 3;
    const int tid = threadIdx.x, lane = tid & 31, w = tid >> 5;
    const int gid = lane >> 2, tig = lane & 3;
    const int r0 = w * 16 + gid, r0g = qb * 128 + r0;

    // Q fragments: fp16 pairs, row pitch 2048 u32
    uint32_t qh[8][4];
#pragma unroll
    for (int c = 0; c < 8; c++) {
        size_t i0 = (size_t)r0g * 2048 + h * 64 + c * 8 + tig;
        qh[c][0] = Qh[i0];     qh[c][1] = Qh[i0 + 8 * 2048];
        qh[c][2] = Qh[i0 + 4]; qh[c][3] = Qh[i0 + 8 * 2048 + 4];
    }

#define FL_ISSUE(kb, buf) do {                                                 \
    _Pragma("unroll")                                                          \
    for (int l = 0; l < 4; l++) {                                              \
        int task = tid + l * 256;                                              \
        int cc = task >> 7, ss = (task >> 1) & 63, hf = task & 1;              \
        cp16(smBase + ((buf) * 4096 + (cc * 64 + ss) * 8 + hf * 4) * 4,        \
             KP2 + ((size_t)(hk * 8 + cc) * SEQ + (kb) * 64 + ss) * 4 + hf * 2); \
    }                                                                          \
    _Pragma("unroll")                                                          \
    for (int l = 0; l < 4; l++) {                                              \
        int task = tid + l * 256;                                              \
        int dd = task >> 3, jj = (task >> 1) & 3, hf = task & 1;               \
        cp16(smBase + (8192 + (buf) * 5120 + (dd * 20 + jj * 4 + hf * 2) * 2) * 4, \
             VP + ((size_t)(hk * 128 + dd) * 256 + (kb) * 4 + jj) * 4 + hf * 2); \
    }                                                                          \
    cp_commit();                                                               \
} while (0)

    float l_[2] = { 0.f, 0.f };
    float o[16][4];
#pragma unroll
    for (int nt = 0; nt < 16; nt++)
#pragma unroll
        for (int q = 0; q < 4; q++) o[nt][q] = 0.f;

    const int kbmax = 2 * qb + 1;
    FL_ISSUE(0, 0);

    for (int kb = 0; kb <= kbmax; kb++) {
        __syncthreads();
        if (kb < kbmax) { FL_ISSUE(kb + 1, (kb + 1) & 1); cp_wait1(); }
        else             cp_wait0();
        __syncthreads();

        const int buf = kb & 1;
        const uint2* Ksp = (const uint2*)sm + buf * 2048;
        const uint2* Vsp = (const uint2*)(sm + 8192) + buf * 2560;

        // S = Q K^T (fp16 single pass): 8 chunks x 8 n-tiles
        float s[8][4];
#pragma unroll
        for (int nt = 0; nt < 8; nt++)
#pragma unroll
            for (int q = 0; q < 4; q++) s[nt][q] = 0.f;
#pragma unroll
        for (int c = 0; c < 8; c++) {
            const uint2* kbp = Ksp + c * 256 + tig;
#pragma unroll
            for (int nt = 0; nt < 8; nt++) {
                uint2 kf = kbp[(nt * 8 + gid) * 4];
                uint32_t b[2] = { kf.x, kf.y };
                mma16h(s[nt], qh[c], b);
            }
        }
        if (kb >= 2 * qb) {
#pragma unroll
            for (int nt = 0; nt < 8; nt++) {
                int col = kb * 64 + nt * 8 + 2 * tig;
                if (col     > r0g)     s[nt][0] = -1e30f;
                if (col + 1 > r0g)     s[nt][1] = -1e30f;
                if (col     > r0g + 8) s[nt][2] = -1e30f;
                if (col + 1 > r0g + 8) s[nt][3] = -1e30f;
            }
        }
        float rs0 = 0.f, rs1 = 0.f;
        uint32_t pa[4][4];
#pragma unroll
        for (int j = 0; j < 4; j++) {
            float e00 = __expf(s[2*j][0]),   e01 = __expf(s[2*j][1]);
            float e02 = __expf(s[2*j][2]),   e03 = __expf(s[2*j][3]);
            float e10 = __expf(s[2*j+1][0]), e11 = __expf(s[2*j+1][1]);
            float e12 = __expf(s[2*j+1][2]), e13 = __expf(s[2*j+1][3]);
            rs0 += (e00 + e01) + (e10 + e11);
            rs1 += (e02 + e03) + (e12 + e13);
            pa[j][0] = h2pack(e00, e01); pa[j][1] = h2pack(e02, e03);
            pa[j][2] = h2pack(e10, e11); pa[j][3] = h2pack(e12, e13);
        }
        rs0 += __shfl_xor_sync(0xffffffffu, rs0, 1);
        rs0 += __shfl_xor_sync(0xffffffffu, rs0, 2);
        rs1 += __shfl_xor_sync(0xffffffffu, rs1, 1);
        rs1 += __shfl_xor_sync(0xffffffffu, rs1, 2);
        l_[0] += rs0; l_[1] += rs1;
#pragma unroll
        for (int j = 0; j < 4; j++) {
#pragma unroll
            for (int nt = 0; nt < 16; nt++) {
                uint2 vv = Vsp[(nt * 8 + gid) * 20 + j * 4 + tig];
                uint32_t b[2] = { vv.x, vv.y };
                mma16h(o[nt], pa[j], b);
            }
        }
    }
    {
        const float il0 = 1.0f / l_[0], il1 = 1.0f / l_[1];
        const int rgO = qb * 8 + w;
#pragma unroll
        for (int j = 0; j < 8; j++) {
            int c = h * 8 + j;
            uint4 u;
            u.x = h2pack(o[2*j][0]   * il0, o[2*j][1]   * il0);
            u.y = h2pack(o[2*j][2]   * il1, o[2*j][3]   * il1);
            u.z = h2pack(o[2*j+1][0] * il0, o[2*j+1][1] * il0);
            u.w = h2pack(o[2*j+1][2] * il1, o[2*j+1][3] * il1);
            OQ[((size_t)(c * 256 + rgO) * 8 + gid) * 4 + tig] = u;
        }
    }
}

// ---------------- launch ----------------
extern "C" void kernel_launch(void* const* d_in, const int* in_sizes, int n_in,
                              void* d_out, int out_size)
{
    const float* X  = (const float*)d_in[0];
    const float* Wq = (const float*)d_in[1];
    const float* Wk = (const float*)d_in[2];
    const float* Wv = (const float*)d_in[3];
    const float* Wo = (const float*)d_in[4];
    const int*  pos = (const int*)d_in[5];
    float* out = (float*)d_out;

    uint4 *XhQ, *OQp;
    uint2 *WqB, *WkB, *WvB, *WoB, *KP2p, *VPp;
    uint32_t *Qhp;
    cudaGetSymbolAddress((void**)&XhQ,  g_XhQ);
    cudaGetSymbolAddress((void**)&WqB,  g_WqB);
    cudaGetSymbolAddress((void**)&WkB,  g_WkB);
    cudaGetSymbolAddress((void**)&WvB,  g_WvB);
    cudaGetSymbolAddress((void**)&WoB,  g_WoB);
    cudaGetSymbolAddress((void**)&Qhp,  g_Qh);
    cudaGetSymbolAddress((void**)&KP2p, g_KP2);
    cudaGetSymbolAddress((void**)&VPp,  g_VP);
    cudaGetSymbolAddress((void**)&OQp,  g_OQ);

    cudaFuncSetAttribute(gemm_f16q<0>, cudaFuncAttributeMaxDynamicSharedMemorySize, F16Q_SMEM_BYTES);
    cudaFuncSetAttribute(gemm_f16q<1>, cudaFuncAttributeMaxDynamicSharedMemorySize, F16Q_SMEM_BYTES);
    cudaFuncSetAttribute(gemm_f16q<2>, cudaFuncAttributeMaxDynamicSharedMemorySize, F16Q_SMEM_BYTES);
    cudaFuncSetAttribute(gemm_f16q<3>, cudaFuncAttributeMaxDynamicSharedMemorySize, F16Q_SMEM_BYTES);
    cudaFuncSetAttribute(flash_mma, cudaFuncAttributeMaxDynamicSharedMemorySize, FL_SMEM_BYTES);

    // prep
    prep_XQh<<<(HID/16) * (SEQ/16) * 32 / 256, 256>>>(X, XhQ);
    prep_W2<<<(HID/16) * DQTOT * 4 / 256, 256>>>(Wq, WqB, DQTOT, DQTOT - 1, 12);
    prep_W2<<<(HID/16) * DKVTOT * 4 / 256, 256>>>(Wk, WkB, DKVTOT, DKVTOT - 1, 9);
    prep_W2<<<(HID/16) * DKVTOT * 4 / 256, 256>>>(Wv, WvB, DKVTOT, DKVTOT - 1, 9);
    prep_W2<<<(DQTOT/16) * HID * 4 / 256, 256>>>(Wo, WoB, HID, HID - 1, 11);

    // projections (all fp16 single-pass) with fused RoPE
    gemm_f16q<1><<<dim3(NHQ, SEQ / 128), 256, F16Q_SMEM_BYTES>>>(
        XhQ, WqB, pos, nullptr, nullptr, Qhp, nullptr, SEQ, DQTOT, HID);
    gemm_f16q<2><<<dim3(NHKV, SEQ / 128), 256, F16Q_SMEM_BYTES>>>(
        XhQ, WkB, pos, nullptr, nullptr, nullptr, KP2p, SEQ, DKVTOT, HID);
    gemm_f16q<3><<<dim3(DKVTOT / 128, SEQ / 128), 256, F16Q_SMEM_BYTES>>>(
        XhQ, WvB, nullptr, nullptr, VPp, nullptr, nullptr, SEQ, DKVTOT, HID);

    // attention (fp16 QK + PV)
    flash_mma<<<dim3(SEQ / 128, NHQ), 256, FL_SMEM_BYTES>>>(Qhp, KP2p, VPp, OQp);

    // output projection
    gemm_f16q<0><<<dim3(HID / 128, SEQ / 128), 256, F16Q_SMEM_BYTES>>>(
        OQp, WoB, nullptr, out, nullptr, nullptr, nullptr, SEQ, HID, DQTOT);
}